// round 15
// baseline (speedup 1.0000x reference)
#include <cuda_runtime.h>
#include <cuda_fp16.h>
#include <math.h>

#define B_   16
#define H_   128
#define W_   128
#define CIN1 256
#define COUT 128

// Scratch (device globals; no allocation). All half2 stored as unsigned.
__device__ unsigned g_xh [(size_t)B_ * 128 * H_ * W_];  // x pairs
__device__ unsigned g_uph[(size_t)B_ *  64 * H_ * W_];  // up pairs
__device__ unsigned g_dnh[(size_t)B_ *  64 * H_ * W_];  // down/merge pairs
__device__ unsigned g_whu[16 * 9 * 1024];               // packed A: [chunk][tap][ci2][co]
__device__ unsigned g_whd[16 * 9 * 1024];
__device__ unsigned g_whp[ 8 * 9 * 1024];

struct BNP { const float *g, *b, *m, *v; };

// ---------------- helpers ----------------
__device__ __forceinline__ void cpa16(unsigned* dst, const unsigned* src, bool ok) {
    unsigned d = (unsigned)__cvta_generic_to_shared(dst);
    int sz = ok ? 16 : 0;
    asm volatile("cp.async.cg.shared.global [%0], [%1], 16, %2;" :: "r"(d), "l"(src), "r"(sz));
}
#define CPCOMMIT() asm volatile("cp.async.commit_group;")
#define CPWAIT(n)  asm volatile("cp.async.wait_group %0;"::"n"(n))

__device__ __forceinline__ void mma_f16(float* c, const unsigned* a, unsigned b0, unsigned b1) {
    asm volatile(
        "mma.sync.aligned.m16n8k16.row.col.f32.f16.f16.f32 "
        "{%0,%1,%2,%3},{%4,%5,%6,%7},{%8,%9},{%0,%1,%2,%3};"
        : "+f"(c[0]), "+f"(c[1]), "+f"(c[2]), "+f"(c[3])
        : "r"(a[0]), "r"(a[1]), "r"(a[2]), "r"(a[3]), "r"(b0), "r"(b1));
}
__device__ __forceinline__ unsigned h2u(float lo, float hi) {
    __half2 h = __floats2half2_rn(lo, hi);
    return *(unsigned*)&h;
}

// smem words (4-deep ring): ws[tap][ci2][136]=9792, xs[row][ci2][136] (4 rows)=4352
#define WS_W 9792
#define XS_W 4352
#define BUF_W (WS_W + XS_W)
#define SMEM_BYTES (4 * BUF_W * 4)    // 226304 B <= 227KB opt-in
// scan buffer (conv3 epilogue): 256 rows x pitch 132 fp32 = 135168 B <= SMEM_BYTES

// ---------------------------------------------------------------------------
// fp16 mma.sync implicit-GEMM 3x3 conv + BN (+ReLU), 4-deep cp.async ring.
// Block=256, tile M=128co x 256px (2 rows x 128w), K streamed 16ci/chunk.
// OUT=0: emit half2 pair tensor. OUT=1: fused reverse-cummax over W (LeftPool),
//        emit fp32 NCHW directly.
// gridDim.z=2 selects (w0,p0,o0) vs (w1,p1,o1) per block (merged conv1+conv2).
// ---------------------------------------------------------------------------
template <int NCC, bool RELU, int OUT>
__global__ __launch_bounds__(256, 1)
void conv_h(const unsigned* __restrict__ xh,
            const unsigned* __restrict__ w0p, const unsigned* __restrict__ w1p,
            BNP p0, BNP p1,
            unsigned* __restrict__ o0, unsigned* __restrict__ o1)
{
    extern __shared__ unsigned sm[];

    const int tid  = threadIdx.x;
    const int b    = blockIdx.y;
    const int h0   = blockIdx.x * 2;
    const int z    = blockIdx.z;

    const unsigned* wh = z ? w1p : w0p;
    const BNP       pp = z ? p1 : p0;
    unsigned*     outv = z ? o1 : o0;

    const int warp = tid >> 5;
    const int lane = tid & 31;
    const int g    = lane >> 2;
    const int tig  = lane & 3;

    const int mwarp  = warp & 1;
    const int nwarp  = warp >> 1;
    const int rloc   = nwarp >> 1;
    const int wn0    = (nwarp & 1) * 64;
    const int cobase = mwarp * 64;

    // static-zero halo cols (3 <- w=-1, 132 <- w=128): 4 bufs x 4 rows x 8 ci2 x 2 cols
    {
        int buf = tid >> 6, rem = tid & 63;
        int colsel = rem & 1, ci2 = (rem >> 1) & 7, row = (rem >> 4) & 3;
        sm[buf * BUF_W + WS_W + row * 1088 + ci2 * 136 + (colsel ? 132 : 3)] = 0u;
    }

    float acc[4][8][4];
#pragma unroll
    for (int mt = 0; mt < 4; mt++)
#pragma unroll
        for (int nt = 0; nt < 8; nt++)
#pragma unroll
            for (int i = 0; i < 4; i++) acc[mt][nt][i] = 0.f;

    auto stage = [&](int c) {
        unsigned* ws = sm + (c & 3) * BUF_W;
        unsigned* xs = ws + WS_W;
#pragma unroll
        for (int k = 0; k < 9; k++) {
            int fi = tid + (k << 8);
            int tap = fi >> 8, rem = fi & 255, ci2 = rem >> 5, cg = rem & 31;
            cpa16(ws + (tap * 8 + ci2) * 136 + cg * 4,
                  wh + (size_t)(c * 9 + tap) * 1024 + ci2 * 128 + cg * 4, true);
        }
#pragma unroll
        for (int k = 0; k < 4; k++) {
            int fi = tid + (k << 8);
            int row = fi >> 8, rem = fi & 255, ci2 = rem >> 5, wg = rem & 31;
            int gh = h0 - 1 + row;
            bool ok = (gh >= 0) && (gh < H_);
            cpa16(xs + row * 1088 + ci2 * 136 + 4 + wg * 4,
                  xh + ((size_t)((b * NCC + c) * 8 + ci2) * H_ + (ok ? gh : 0)) * W_ + wg * 4,
                  ok);
        }
    };

    stage(0); CPCOMMIT();
    stage(1); CPCOMMIT();
    stage(2); CPCOMMIT();

    for (int c = 0; c < NCC; c++) {
        // ensure stage(c) complete (pending groups behind it vary near the tail)
        if (c + 2 < NCC)      { CPWAIT(2); }
        else if (c + 1 < NCC) { CPWAIT(1); }
        else                  { CPWAIT(0); }
        __syncthreads();   // stage(c) visible; all warps done with compute(c-1)
        if (c + 3 < NCC) { stage(c + 3); CPCOMMIT(); }   // buf (c+3)&3 == (c-1)&3, free

        const unsigned* ws = sm + (c & 3) * BUF_W;
        const unsigned* xs = ws + WS_W;

#pragma unroll
        for (int dh = 0; dh < 3; dh++)
#pragma unroll
            for (int dw = 0; dw < 3; dw++) {
                const int tap = dh * 3 + dw;
                const unsigned* wr0 = ws + (tap * 8 + tig) * 136;
                const unsigned* wr1 = ws + (tap * 8 + tig + 4) * 136;
                unsigned a[4][4];
#pragma unroll
                for (int mt = 0; mt < 4; mt++) {
                    int cb = cobase + mt * 16 + g;
                    a[mt][0] = wr0[cb];
                    a[mt][1] = wr0[cb + 8];
                    a[mt][2] = wr1[cb];
                    a[mt][3] = wr1[cb + 8];
                }
                const unsigned* p0 = xs + (rloc + dh) * 1088 + tig * 136 + wn0 + g + dw + 3;
                const unsigned* p1 = p0 + 4 * 136;
#pragma unroll
                for (int nt = 0; nt < 8; nt++) {
                    unsigned b0 = p0[nt * 8];
                    unsigned b1 = p1[nt * 8];
#pragma unroll
                    for (int mt = 0; mt < 4; mt++)
                        mma_f16(acc[mt][nt], a[mt], b0, b1);
                }
            }
    }

    // ---- epilogue: BN (+ReLU) ----
    const int h = h0 + rloc;
    if (OUT == 0) {
#pragma unroll
        for (int mt = 0; mt < 4; mt++) {
            int ca = cobase + mt * 16 + g;
            int cb2 = ca + 8;
            float inva = pp.g[ca]  * rsqrtf(pp.v[ca]  + 1e-5f);
            float bia  = pp.b[ca]  - pp.m[ca]  * inva;
            float invb = pp.g[cb2] * rsqrtf(pp.v[cb2] + 1e-5f);
            float bib  = pp.b[cb2] - pp.m[cb2] * invb;
            int j = (mwarp * 4 + mt) * 8 + g;   // pair row
            unsigned* rp = outv + ((size_t)(b * 64 + j) * H_ + h) * W_;
#pragma unroll
            for (int nt = 0; nt < 8; nt++) {
                int w0 = wn0 + nt * 8 + 2 * tig;
                float v0 = acc[mt][nt][0] * inva + bia;
                float v1 = acc[mt][nt][1] * inva + bia;
                float v2 = acc[mt][nt][2] * invb + bib;
                float v3 = acc[mt][nt][3] * invb + bib;
                if (RELU) { v0=fmaxf(v0,0.f); v1=fmaxf(v1,0.f); v2=fmaxf(v2,0.f); v3=fmaxf(v3,0.f); }
                uint2 q; q.x = h2u(v0, v2); q.y = h2u(v1, v3);
                *(uint2*)(rp + w0) = q;
            }
        }
    } else {
        // ---- fused LeftPool: BN -> smem -> reverse cummax over W -> fp32 NCHW ----
        float* sc = (float*)sm;               // [256 rows (co*2+r)][pitch 132]
        __syncthreads();                      // mainloop smem reads complete everywhere
#pragma unroll
        for (int mt = 0; mt < 4; mt++) {
            int ca = cobase + mt * 16 + g;
            int cb2 = ca + 8;
            float inva = pp.g[ca]  * rsqrtf(pp.v[ca]  + 1e-5f);
            float bia  = pp.b[ca]  - pp.m[ca]  * inva;
            float invb = pp.g[cb2] * rsqrtf(pp.v[cb2] + 1e-5f);
            float bib  = pp.b[cb2] - pp.m[cb2] * invb;
            float* r0 = sc + (ca * 2 + rloc) * 132;
            float* r1 = sc + (cb2 * 2 + rloc) * 132;
#pragma unroll
            for (int nt = 0; nt < 8; nt++) {
                int w0 = wn0 + nt * 8 + 2 * tig;
                *(float2*)(r0 + w0) = make_float2(acc[mt][nt][0] * inva + bia,
                                                  acc[mt][nt][1] * inva + bia);
                *(float2*)(r1 + w0) = make_float2(acc[mt][nt][2] * invb + bib,
                                                  acc[mt][nt][3] * invb + bib);
            }
        }
        __syncthreads();
        // per-thread serial reverse max-scan of one (co,r) row
        {
            float* rw = sc + tid * 132;
            float run = -INFINITY;
#pragma unroll 4
            for (int w = W_ - 1; w >= 0; w--) {
                run = fmaxf(run, rw[w]);
                rw[w] = run;
            }
        }
        __syncthreads();
        // coalesced float4 store to fp32 NCHW output
        float* outf = (float*)outv;
#pragma unroll
        for (int k = 0; k < 32; k++) {
            int idx4 = tid + (k << 8);        // 8192 float4s
            int co = idx4 >> 6;
            int r  = (idx4 >> 5) & 1;
            int w4 = idx4 & 31;
            float4 q = *(float4*)(sc + (co * 2 + r) * 132 + w4 * 4);
            ((float4*)(outf + (((size_t)b * COUT + co) * H_ + h0 + r) * W_))[w4] = q;
        }
    }
}

// ---------------------------------------------------------------------------
// Merged prep: xpose (2-wide) + all three weight packs in ONE kernel.
// ---------------------------------------------------------------------------
#define XP_BLKS 65536          // (B*128*H*W/2) / 256
#define WP1_BLKS 576           // (128*9*128)/256
#define WP3_BLKS 288           // (64*9*128)/256

__device__ __forceinline__ void wpack_body(int idx, int CIN, bool PAIR8,
                                           const float* __restrict__ w,
                                           unsigned* __restrict__ wo)
{
    int co = idx & 127;
    int tap = (idx >> 7) % 9;
    int jg = idx / (9 * 128);
    int ca, cbb;
    if (PAIR8) { ca = (jg >> 3) * 16 + (jg & 7); cbb = ca + 8; }
    else       { ca = 2 * jg;                    cbb = ca + 1; }
    float wa = w[((size_t)co * CIN + ca)  * 9 + tap];
    float wb = w[((size_t)co * CIN + cbb) * 9 + tap];
    wo[((size_t)((jg >> 3) * 9 + tap)) * 1024 + (jg & 7) * 128 + co] = h2u(wa, wb);
}

__global__ void prep_all(const float* __restrict__ x, unsigned* __restrict__ xh,
                         const float* __restrict__ w_up,   unsigned* __restrict__ whu,
                         const float* __restrict__ w_down, unsigned* __restrict__ whd,
                         const float* __restrict__ w_p,    unsigned* __restrict__ whp)
{
    int blk = blockIdx.x;
    if (blk < XP_BLKS) {
        size_t e = (size_t)blk * 256 + threadIdx.x;   // pair-of-w index
        int w2  = (int)(e & 63);
        int h   = (int)((e >> 6) & 127);
        int ci2 = (int)((e >> 13) & 127);
        int b   = (int)(e >> 20);
        const float* p0 = x + (((size_t)b * CIN1 + 2 * ci2)     * H_ + h) * W_ + 2 * w2;
        const float* p1 = x + (((size_t)b * CIN1 + 2 * ci2 + 1) * H_ + h) * W_ + 2 * w2;
        float2 a = *(const float2*)p0;
        float2 c = *(const float2*)p1;
        uint2 q; q.x = h2u(a.x, c.x); q.y = h2u(a.y, c.y);
        *(uint2*)(xh + (((size_t)b * 128 + ci2) * H_ + h) * W_ + 2 * w2) = q;
    } else if (blk < XP_BLKS + WP1_BLKS) {
        int idx = (blk - XP_BLKS) * 256 + threadIdx.x;
        wpack_body(idx, CIN1, false, w_up, whu);
    } else if (blk < XP_BLKS + 2 * WP1_BLKS) {
        int idx = (blk - XP_BLKS - WP1_BLKS) * 256 + threadIdx.x;
        wpack_body(idx, CIN1, false, w_down, whd);
    } else {
        int idx = (blk - XP_BLKS - 2 * WP1_BLKS) * 256 + threadIdx.x;
        wpack_body(idx, COUT, true, w_p, whp);
    }
}

// ---------------------------------------------------------------------------
// TopPool (reverse cummax over H) + add, uint2-vectorized (4 halfs/thread).
// ---------------------------------------------------------------------------
__global__ void tpool_h(const uint2* __restrict__ up, const uint2* __restrict__ dn,
                        uint2* __restrict__ mg)
{
    int idx = blockIdx.x * 256 + threadIdx.x;   // B*64*(W/2)
    int w2 = idx & 63;
    int bj = idx >> 6;
    size_t base = (size_t)bj * H_ * 64 + w2;
    unsigned ru = 0xFC00FC00u;                  // half2(-inf,-inf)
    __half2 run0 = *(__half2*)&ru;
    __half2 run1 = run0;
#pragma unroll 4
    for (int h = H_ - 1; h >= 0; h--) {
        size_t o = base + (size_t)h * 64;
        uint2 u = up[o];
        uint2 d = dn[o];
        run0 = __hmax2(run0, *(__half2*)&u.x);
        run1 = __hmax2(run1, *(__half2*)&u.y);
        __half2 m0 = __hadd2(run0, *(__half2*)&d.x);
        __half2 m1 = __hadd2(run1, *(__half2*)&d.y);
        uint2 q; q.x = *(unsigned*)&m0; q.y = *(unsigned*)&m1;
        mg[o] = q;
    }
}

// ---------------------------------------------------------------------------
extern "C" void kernel_launch(void* const* d_in, const int* in_sizes, int n_in,
                              void* d_out, int out_size)
{
    const float* x      = (const float*)d_in[0];
    const float* w_up   = (const float*)d_in[1];
    const float* up_g   = (const float*)d_in[2];
    const float* up_b   = (const float*)d_in[3];
    const float* up_m   = (const float*)d_in[4];
    const float* up_v   = (const float*)d_in[5];
    const float* w_down = (const float*)d_in[6];
    const float* dn_g   = (const float*)d_in[7];
    const float* dn_b   = (const float*)d_in[8];
    const float* dn_m   = (const float*)d_in[9];
    const float* dn_v   = (const float*)d_in[10];
    const float* w_p    = (const float*)d_in[11];
    const float* p_g    = (const float*)d_in[12];
    const float* p_b    = (const float*)d_in[13];
    const float* p_m    = (const float*)d_in[14];
    const float* p_v    = (const float*)d_in[15];
    float* outp = (float*)d_out;

    unsigned *xh, *uph, *dnh, *whu, *whd, *whp;
    cudaGetSymbolAddress((void**)&xh,  g_xh);
    cudaGetSymbolAddress((void**)&uph, g_uph);
    cudaGetSymbolAddress((void**)&dnh, g_dnh);
    cudaGetSymbolAddress((void**)&whu, g_whu);
    cudaGetSymbolAddress((void**)&whd, g_whd);
    cudaGetSymbolAddress((void**)&whp, g_whp);

    cudaFuncSetAttribute(conv_h<16, true,  0>, cudaFuncAttributeMaxDynamicSharedMemorySize, SMEM_BYTES);
    cudaFuncSetAttribute(conv_h< 8, false, 1>, cudaFuncAttributeMaxDynamicSharedMemorySize, SMEM_BYTES);

    // prep (single kernel: xpose + all weight packs)
    prep_all<<<XP_BLKS + 2 * WP1_BLKS + WP3_BLKS, 256>>>(
        x, xh, w_up, whu, w_down, whd, w_p, whp);

    BNP pup = { up_g, up_b, up_m, up_v };
    BNP pdn = { dn_g, dn_b, dn_m, dn_v };
    BNP ppp = { p_g,  p_b,  p_m,  p_v  };

    // conv1 + conv2 merged (z selects weight/BN/output set)
    dim3 g12(H_ / 2, B_, 2);
    conv_h<16, true, 0><<<g12, 256, SMEM_BYTES>>>(xh, whu, whd, pup, pdn, uph, dnh);
    // merge = toppool(up) + down
    tpool_h<<<(B_ * 64 * (W_ / 2)) / 256, 256>>>((const uint2*)uph, (const uint2*)dnh, (uint2*)dnh);
    // conv3 + BN + fused LeftPool -> fp32 output
    dim3 g3(H_ / 2, B_, 1);
    conv_h<8, false, 1><<<g3, 256, SMEM_BYTES>>>(dnh, whp, whp, ppp, ppp,
                                                 (unsigned*)outp, (unsigned*)outp);
}

// round 16
// speedup vs baseline: 1.0585x; 1.0585x over previous
#include <cuda_runtime.h>
#include <cuda_fp16.h>
#include <math.h>

#define B_   16
#define H_   128
#define W_   128
#define CIN1 256
#define COUT 128

// Scratch (device globals; no allocation).
// xh / uph / dnh layout: [b][chunk][h][px-ish w][ci2(8 half2)]  (1024 words per (b,chunk,h))
__device__ unsigned g_xh [(size_t)B_ * 16 * H_ * 1024];
__device__ unsigned g_uph[(size_t)B_ *  8 * H_ * 1024];
__device__ unsigned g_dnh[(size_t)B_ *  8 * H_ * 1024];
// packed A: [chunk][tap][co][ci2(8)]
__device__ unsigned g_whu[16 * 9 * 1024];
__device__ unsigned g_whd[16 * 9 * 1024];
__device__ unsigned g_whp[ 8 * 9 * 1024];

struct BNP { const float *g, *b, *m, *v; };

// ---------------- helpers ----------------
__device__ __forceinline__ void cpa16(unsigned dst, const unsigned* src, bool ok) {
    int sz = ok ? 16 : 0;
    asm volatile("cp.async.ca.shared.global [%0], [%1], 16, %2;" :: "r"(dst), "l"(src), "r"(sz));
}
#define CPCOMMIT() asm volatile("cp.async.commit_group;")
#define CPWAIT(n)  asm volatile("cp.async.wait_group %0;"::"n"(n))

__device__ __forceinline__ void mma_f16(float* c, const unsigned* a, unsigned b0, unsigned b1) {
    asm volatile(
        "mma.sync.aligned.m16n8k16.row.col.f32.f16.f16.f32 "
        "{%0,%1,%2,%3},{%4,%5,%6,%7},{%8,%9},{%0,%1,%2,%3};"
        : "+f"(c[0]), "+f"(c[1]), "+f"(c[2]), "+f"(c[3])
        : "r"(a[0]), "r"(a[1]), "r"(a[2]), "r"(a[3]), "r"(b0), "r"(b1));
}
__device__ __forceinline__ void ldsm4(unsigned* r, unsigned addr) {
    asm volatile("ldmatrix.sync.aligned.m8n8.x4.shared.b16 {%0,%1,%2,%3}, [%4];"
                 : "=r"(r[0]), "=r"(r[1]), "=r"(r[2]), "=r"(r[3]) : "r"(addr));
}
__device__ __forceinline__ unsigned h2u(float lo, float hi) {
    __half2 h = __floats2half2_rn(lo, hi);
    return *(unsigned*)&h;
}
__device__ __forceinline__ unsigned smem_u32(const void* p) {
    unsigned a;
    asm("{ .reg .u64 t; cvta.to.shared.u64 t, %1; cvt.u32.u64 %0, t; }" : "=r"(a) : "l"(p));
    return a;
}

// smem bytes per buffer: ws 9*128*32 = 36864, xs 4 rows * 132px * 32 = 16896
#define WS_B 36864
#define XS_B 16896
#define BUF_B (WS_B + XS_B)                  // 53760
#define SMEM_BYTES (3 * BUF_B)               // 161280
#define XROW_B 4224                          // 132*32 bytes per xs h-row

// ---------------------------------------------------------------------------
// fp16 mma.sync implicit-GEMM 3x3 conv + BN (+ReLU), 3-deep cp.async ring,
// ldmatrix.x4 fragment loads from 16B-XOR-swizzled smem.
// Block=256, tile M=128co x 256px (2 rows x 128w), K streamed 16ci/chunk.
// OUT=0: emit interleaved half2 tensor. OUT=1: fused LeftPool -> fp32 NCHW.
// gridDim.z=2 selects (w0,p0,o0)/(w1,p1,o1) (merged conv1+conv2).
// ---------------------------------------------------------------------------
template <int NCC, bool RELU, int OUT>
__global__ __launch_bounds__(256, 1)
void conv_h(const unsigned* __restrict__ xh,
            const unsigned* __restrict__ w0p, const unsigned* __restrict__ w1p,
            BNP p0, BNP p1,
            unsigned* __restrict__ o0, unsigned* __restrict__ o1)
{
    extern __shared__ unsigned sm[];
    const unsigned smb = smem_u32(sm);

    const int tid  = threadIdx.x;
    const int b    = blockIdx.y;
    const int h0   = blockIdx.x * 2;
    const int z    = blockIdx.z;

    const unsigned* wh = z ? w1p : w0p;
    const BNP       pp = z ? p1 : p0;
    unsigned*     outv = z ? o1 : o0;

    const int warp = tid >> 5;
    const int lane = tid & 31;
    const int g    = lane >> 2;
    const int tig  = lane & 3;

    const int mwarp  = warp & 1;
    const int nwarp  = warp >> 1;
    const int rloc   = nwarp >> 1;
    const int wn0    = (nwarp & 1) * 64;
    const int cobase = mwarp * 64;

    // ---- per-lane ldmatrix byte offsets (chunk/buffer independent) ----
    // A: rows = co (32B each, swizzled), matrices [co-lo,k-lo][co-hi,k-lo][co-lo,k-hi][co-hi,k-hi]
    const int arow  = cobase + (lane & 15);
    const int ahalf = lane >> 4;
    const unsigned aoff0 = arow * 32 + ((ahalf ^ ((arow >> 2) & 1)) << 4);
    // B: rows = px (32B each, swizzled), matrices [nt-lo k-lo][nt-lo k-hi][nt-hi k-lo][nt-hi k-hi]
    const int bl    = (lane & 7) + ((lane >> 4) << 3);
    const int bhalf = (lane >> 3) & 1;
    unsigned boff[4][3];
#pragma unroll
    for (int ntp = 0; ntp < 4; ntp++)
#pragma unroll
        for (int dw = 0; dw < 3; dw++) {
            int px = wn0 + ntp * 16 + bl + dw;   // px = gw+1 slot
            boff[ntp][dw] = px * 32 + ((bhalf ^ ((px >> 2) & 1)) << 4);
        }

    // ---- static-zero halo px (px0 <- w=-1; px129..131 pad): 3 bufs x 4 rows x 8 units ----
    if (tid < 96) {
        int buf = tid / 32, rem = tid % 32, r = rem >> 3, ui = rem & 7;
        int u = (ui < 2) ? ui : (256 + ui);              // units {0,1,258..263}
        unsigned ph = u ^ ((u >> 3) & 1);
        *(uint4*)((char*)sm + buf * BUF_B + WS_B + r * XROW_B + ph * 16) = make_uint4(0, 0, 0, 0);
    }

    float acc[4][8][4];
#pragma unroll
    for (int mt = 0; mt < 4; mt++)
#pragma unroll
        for (int nt = 0; nt < 8; nt++)
#pragma unroll
            for (int i = 0; i < 4; i++) acc[mt][nt][i] = 0.f;

    auto stage = [&](int c) {
        unsigned wsd = smb + (c % 3) * BUF_B;
        unsigned xsd = wsd + WS_B;
        const unsigned* wsrc = wh + (size_t)c * 9216;
        // weights: 2304 16B units, contiguous source, swizzled dest
#pragma unroll
        for (int k = 0; k < 9; k++) {
            int fi = tid + (k << 8);
            unsigned ph = fi ^ ((fi >> 3) & 1);
            cpa16(wsd + ph * 16, wsrc + fi * 4, true);
        }
        // x: 4 h-rows x 256 units (128 w x 2), dest px slot = w+1, swizzled
#pragma unroll
        for (int k = 0; k < 4; k++) {
            int fi = tid + (k << 8);
            int r = fi >> 8, j = fi & 255;
            int gh = h0 - 1 + r;
            bool ok = (gh >= 0) && (gh < H_);
            int u = j + 2;
            unsigned ph = u ^ ((u >> 3) & 1);
            cpa16(xsd + r * XROW_B + ph * 16,
                  xh + ((size_t)(b * NCC + c) * H_ + (ok ? gh : 0)) * 1024 + j * 4, ok);
        }
    };

    stage(0); CPCOMMIT();
    stage(1); CPCOMMIT();

    for (int c = 0; c < NCC; c++) {
        if (c + 1 < NCC) { CPWAIT(1); } else { CPWAIT(0); }
        __syncthreads();   // stage(c) visible; all warps done with compute(c-1)
        if (c + 2 < NCC) { stage(c + 2); CPCOMMIT(); }   // buf (c+2)%3 == (c-1)%3, free

        const unsigned wsb_ = smb + (c % 3) * BUF_B;
        const unsigned xsb_ = wsb_ + WS_B;

#pragma unroll
        for (int dh = 0; dh < 3; dh++) {
            const unsigned xrow = xsb_ + (rloc + dh) * XROW_B;
#pragma unroll
            for (int dw = 0; dw < 3; dw++) {
                const unsigned wtap = wsb_ + (dh * 3 + dw) * 4096 + aoff0;
                unsigned a[4][4];
#pragma unroll
                for (int mt = 0; mt < 4; mt++)
                    ldsm4(a[mt], wtap + mt * 512);
#pragma unroll
                for (int ntp = 0; ntp < 4; ntp++) {
                    unsigned bb[4];
                    ldsm4(bb, xrow + boff[ntp][dw]);
#pragma unroll
                    for (int mt = 0; mt < 4; mt++) {
                        mma_f16(acc[mt][2 * ntp],     a[mt], bb[0], bb[1]);
                        mma_f16(acc[mt][2 * ntp + 1], a[mt], bb[2], bb[3]);
                    }
                }
            }
        }
    }

    // ---- epilogue: BN (+ReLU) ----
    const int h = h0 + rloc;
    if (OUT == 0) {
#pragma unroll
        for (int mt = 0; mt < 4; mt++) {
            int ca = cobase + mt * 16 + g;     // pair lo
            int cb2 = ca + 8;                  // pair hi
            float inva = pp.g[ca]  * rsqrtf(pp.v[ca]  + 1e-5f);
            float bia  = pp.b[ca]  - pp.m[ca]  * inva;
            float invb = pp.g[cb2] * rsqrtf(pp.v[cb2] + 1e-5f);
            float bib  = pp.b[cb2] - pp.m[cb2] * invb;
            int j8 = mwarp * 4 + mt;           // chunk index of pair row
            unsigned* rp = outv + ((size_t)(b * 8 + j8) * H_ + h) * 1024 + g;
#pragma unroll
            for (int nt = 0; nt < 8; nt++) {
                int w0 = wn0 + nt * 8 + 2 * tig;
                float v0 = acc[mt][nt][0] * inva + bia;
                float v1 = acc[mt][nt][1] * inva + bia;
                float v2 = acc[mt][nt][2] * invb + bib;
                float v3 = acc[mt][nt][3] * invb + bib;
                if (RELU) { v0=fmaxf(v0,0.f); v1=fmaxf(v1,0.f); v2=fmaxf(v2,0.f); v3=fmaxf(v3,0.f); }
                rp[w0 * 8]     = h2u(v0, v2);
                rp[w0 * 8 + 8] = h2u(v1, v3);
            }
        }
    } else {
        // ---- fused LeftPool: BN -> smem -> reverse cummax over W -> fp32 NCHW ----
        float* sc = (float*)sm;               // [256 rows (co*2+r)][pitch 132]
        __syncthreads();                      // mainloop smem reads complete everywhere
#pragma unroll
        for (int mt = 0; mt < 4; mt++) {
            int ca = cobase + mt * 16 + g;
            int cb2 = ca + 8;
            float inva = pp.g[ca]  * rsqrtf(pp.v[ca]  + 1e-5f);
            float bia  = pp.b[ca]  - pp.m[ca]  * inva;
            float invb = pp.g[cb2] * rsqrtf(pp.v[cb2] + 1e-5f);
            float bib  = pp.b[cb2] - pp.m[cb2] * invb;
            float* r0 = sc + (ca * 2 + rloc) * 132;
            float* r1 = sc + (cb2 * 2 + rloc) * 132;
#pragma unroll
            for (int nt = 0; nt < 8; nt++) {
                int w0 = wn0 + nt * 8 + 2 * tig;
                *(float2*)(r0 + w0) = make_float2(acc[mt][nt][0] * inva + bia,
                                                  acc[mt][nt][1] * inva + bia);
                *(float2*)(r1 + w0) = make_float2(acc[mt][nt][2] * invb + bib,
                                                  acc[mt][nt][3] * invb + bib);
            }
        }
        __syncthreads();
        {
            float* rw = sc + tid * 132;
            float run = -INFINITY;
#pragma unroll 4
            for (int w = W_ - 1; w >= 0; w--) {
                run = fmaxf(run, rw[w]);
                rw[w] = run;
            }
        }
        __syncthreads();
        float* outf = (float*)outv;
#pragma unroll
        for (int k = 0; k < 32; k++) {
            int idx4 = tid + (k << 8);        // 8192 float4s
            int co = idx4 >> 6;
            int r  = (idx4 >> 5) & 1;
            int w4 = idx4 & 31;
            float4 q = *(float4*)(sc + (co * 2 + r) * 132 + w4 * 4);
            ((float4*)(outf + (((size_t)b * COUT + co) * H_ + h0 + r) * W_))[w4] = q;
        }
    }
}

// ---------------------------------------------------------------------------
// Merged prep: xpose (smem transpose per (b,c,h)) + all weight packs.
// ---------------------------------------------------------------------------
#define XP_BLKS 32768          // B * 16 chunks * H
#define WP1_BLKS 576           // 16*9*1024 words / 256
#define WP3_BLKS 288           // 8*9*1024 words / 256

__device__ __forceinline__ void wpack_body(int idx, int CIN, bool PAIR8,
                                           const float* __restrict__ w,
                                           unsigned* __restrict__ wo)
{
    // idx = ((c*9+tap)*128 + co)*8 + ci2
    int ci2 = idx & 7;
    int co  = (idx >> 3) & 127;
    int tap = (idx >> 10) % 9;
    int c   = idx / (9 * 1024);
    int ca, cbb;
    if (PAIR8) { ca = 16 * c + ci2; cbb = ca + 8; }
    else       { ca = c * 16 + 2 * ci2; cbb = ca + 1; }
    float wa = w[((size_t)co * CIN + ca)  * 9 + tap];
    float wb = w[((size_t)co * CIN + cbb) * 9 + tap];
    wo[idx] = h2u(wa, wb);
}

__global__ void prep_all(const float* __restrict__ x, unsigned* __restrict__ xh,
                         const float* __restrict__ w_up,   unsigned* __restrict__ whu,
                         const float* __restrict__ w_down, unsigned* __restrict__ whd,
                         const float* __restrict__ w_p,    unsigned* __restrict__ whp)
{
    __shared__ float sx[16 * 130];
    int blk = blockIdx.x;
    int tid = threadIdx.x;
    if (blk < XP_BLKS) {
        int h  = blk & 127;
        int bc = blk >> 7;          // b*16 + c
#pragma unroll
        for (int k = 0; k < 8; k++) {
            int e = tid + (k << 8);             // 0..2047
            int cil = e >> 7, w = e & 127;
            sx[cil * 130 + w] =
                x[(((size_t)(bc >> 4) * CIN1 + (bc & 15) * 16 + cil) * H_ + h) * W_ + w];
        }
        __syncthreads();
#pragma unroll
        for (int k = 0; k < 4; k++) {
            int o = tid + (k << 8);             // w*8 + ci2
            int ci2 = o & 7, w = o >> 3;
            xh[((size_t)bc * H_ + h) * 1024 + o] =
                h2u(sx[(2 * ci2) * 130 + w], sx[(2 * ci2 + 1) * 130 + w]);
        }
    } else if (blk < XP_BLKS + WP1_BLKS) {
        wpack_body((blk - XP_BLKS) * 256 + tid, CIN1, false, w_up, whu);
    } else if (blk < XP_BLKS + 2 * WP1_BLKS) {
        wpack_body((blk - XP_BLKS - WP1_BLKS) * 256 + tid, CIN1, false, w_down, whd);
    } else {
        wpack_body((blk - XP_BLKS - 2 * WP1_BLKS) * 256 + tid, COUT, true, w_p, whp);
    }
}

// ---------------------------------------------------------------------------
// TopPool (reverse cummax over H) + add on interleaved half2 tensors.
// Column = (b*8+c, word-pair q); h-stride = 512 uint2.
// ---------------------------------------------------------------------------
__global__ void tpool_h(const uint2* __restrict__ up, const uint2* __restrict__ dn,
                        uint2* __restrict__ mg)
{
    int idx = blockIdx.x * 256 + threadIdx.x;   // 16*8*512 = 65536
    int q  = idx & 511;
    int bc = idx >> 9;
    size_t base = (size_t)bc * H_ * 512 + q;
    unsigned ru = 0xFC00FC00u;                  // half2(-inf,-inf)
    __half2 run0 = *(__half2*)&ru;
    __half2 run1 = run0;
#pragma unroll 4
    for (int h = H_ - 1; h >= 0; h--) {
        size_t o = base + (size_t)h * 512;
        uint2 u = up[o];
        uint2 d = dn[o];
        run0 = __hmax2(run0, *(__half2*)&u.x);
        run1 = __hmax2(run1, *(__half2*)&u.y);
        __half2 m0 = __hadd2(run0, *(__half2*)&d.x);
        __half2 m1 = __hadd2(run1, *(__half2*)&d.y);
        uint2 qq; qq.x = *(unsigned*)&m0; qq.y = *(unsigned*)&m1;
        mg[o] = qq;
    }
}

// ---------------------------------------------------------------------------
extern "C" void kernel_launch(void* const* d_in, const int* in_sizes, int n_in,
                              void* d_out, int out_size)
{
    const float* x      = (const float*)d_in[0];
    const float* w_up   = (const float*)d_in[1];
    const float* up_g   = (const float*)d_in[2];
    const float* up_b   = (const float*)d_in[3];
    const float* up_m   = (const float*)d_in[4];
    const float* up_v   = (const float*)d_in[5];
    const float* w_down = (const float*)d_in[6];
    const float* dn_g   = (const float*)d_in[7];
    const float* dn_b   = (const float*)d_in[8];
    const float* dn_m   = (const float*)d_in[9];
    const float* dn_v   = (const float*)d_in[10];
    const float* w_p    = (const float*)d_in[11];
    const float* p_g    = (const float*)d_in[12];
    const float* p_b    = (const float*)d_in[13];
    const float* p_m    = (const float*)d_in[14];
    const float* p_v    = (const float*)d_in[15];
    float* outp = (float*)d_out;

    unsigned *xh, *uph, *dnh, *whu, *whd, *whp;
    cudaGetSymbolAddress((void**)&xh,  g_xh);
    cudaGetSymbolAddress((void**)&uph, g_uph);
    cudaGetSymbolAddress((void**)&dnh, g_dnh);
    cudaGetSymbolAddress((void**)&whu, g_whu);
    cudaGetSymbolAddress((void**)&whd, g_whd);
    cudaGetSymbolAddress((void**)&whp, g_whp);

    cudaFuncSetAttribute(conv_h<16, true,  0>, cudaFuncAttributeMaxDynamicSharedMemorySize, SMEM_BYTES);
    cudaFuncSetAttribute(conv_h< 8, false, 1>, cudaFuncAttributeMaxDynamicSharedMemorySize, SMEM_BYTES);

    // prep (single kernel: xpose + all weight packs)
    prep_all<<<XP_BLKS + 2 * WP1_BLKS + WP3_BLKS, 256>>>(
        x, xh, w_up, whu, w_down, whd, w_p, whp);

    BNP pup = { up_g, up_b, up_m, up_v };
    BNP pdn = { dn_g, dn_b, dn_m, dn_v };
    BNP ppp = { p_g,  p_b,  p_m,  p_v  };

    // conv1 + conv2 merged (z selects weight/BN/output set)
    dim3 g12(H_ / 2, B_, 2);
    conv_h<16, true, 0><<<g12, 256, SMEM_BYTES>>>(xh, whu, whd, pup, pdn, uph, dnh);
    // merge = toppool(up) + down
    tpool_h<<<65536 / 256, 256>>>((const uint2*)uph, (const uint2*)dnh, (uint2*)dnh);
    // conv3 + BN + fused LeftPool -> fp32 output
    dim3 g3(H_ / 2, B_, 1);
    conv_h<8, false, 1><<<g3, 256, SMEM_BYTES>>>(dnh, whp, whp, ppp, ppp,
                                                 (unsigned*)outp, (unsigned*)outp);
}